// round 3
// baseline (speedup 1.0000x reference)
#include <cuda_runtime.h>
#include <cstdint>

// out[row, n] = sum_t u[row, t] * K[n, 1023 - t]   (row = (b*2+e)*64+d)
// Skinny GEMM 512x64x1024, fp32. One block = 4 rows x 64 n, t split 4-ways
// across thread groups (q), reduced in smem at the end.

#define T_LEN   1024
#define N_ORD   64
#define RPB     4            // rows per block
#define TT      256          // K tile width (t)
#define KPITCH  260          // 260 % 32 == 4  -> conflict-free LDS.128 across lanes
#define NTILES  (T_LEN / TT)
#define THREADS 256
#define NBLOCKS (512 / RPB)  // 128

__device__ __forceinline__ void cp_async16(void* dst, const void* src) {
    unsigned s = (unsigned)__cvta_generic_to_shared(dst);
    asm volatile("cp.async.cg.shared.global [%0], [%1], 16;\n" :: "r"(s), "l"(src));
}
__device__ __forceinline__ void cp_commit() {
    asm volatile("cp.async.commit_group;\n");
}
template <int N>
__device__ __forceinline__ void cp_wait() {
    asm volatile("cp.async.wait_group %0;\n" :: "n"(N));
}

extern __shared__ float smem[];
// layout: u_s[4*1024] | kbuf0[64*KPITCH] | kbuf1[64*KPITCH]
// total = (4096 + 2*64*260) * 4 = 149504 bytes (dynamic smem)

__global__ void __launch_bounds__(THREADS, 1)
hippo_last_kernel(const float* __restrict__ U,
                  const float* __restrict__ K,
                  float* __restrict__ out)
{
    float* u_s = smem;                         // 4096 floats
    float* kb0 = smem + RPB * T_LEN;           // 64*260 floats
    float* kb1 = kb0 + N_ORD * KPITCH;

    const int tid = threadIdx.x;
    const int q   = tid >> 6;                  // t-quarter within tile
    const int n   = tid & 63;

    const float* Ublk = U + (size_t)blockIdx.x * RPB * T_LEN;

    // ---- load the block's 4 u-rows into smem (float4, coalesced) ----
    {
        const float4* src = (const float4*)Ublk;
        float4*       dst = (float4*)u_s;
        #pragma unroll
        for (int w = 0; w < (RPB * T_LEN / 4) / THREADS; ++w)
            dst[tid + THREADS * w] = src[tid + THREADS * w];
    }

    // ---- K tile producer: tile i covers K[:, J0 .. J0+TT), J0 = 768 - 256*i ----
    auto issue_tile = [&](int i, float* kb) {
        const int J0 = (T_LEN - TT) - TT * i;
        #pragma unroll
        for (int w = 0; w < (N_ORD * TT / 4) / THREADS; ++w) {
            int idx = tid + THREADS * w;       // 0 .. 4095
            int nn  = idx >> 6;                // K row
            int c   = (idx & 63) << 2;         // float4 column (elements)
            cp_async16(&kb[nn * KPITCH + c], &K[nn * T_LEN + J0 + c]);
        }
        cp_commit();
    };
    issue_tile(0, kb0);

    float acc[RPB] = {0.f, 0.f, 0.f, 0.f};

    #pragma unroll
    for (int i = 0; i < NTILES; ++i) {
        if (i + 1 < NTILES) {
            issue_tile(i + 1, ((i + 1) & 1) ? kb1 : kb0);
            cp_wait<1>();
        } else {
            cp_wait<0>();
        }
        __syncthreads();

        const float* kb = ((i & 1) ? kb1 : kb0) + n * KPITCH;
        const int tbase = i * TT;              // tile's global t offset

        #pragma unroll
        for (int it = 0; it < 16; ++it) {
            const int s = q * 64 + it * 4;     // local t within tile
            // K index within tile for t = tbase+s is (TT-1) - s; float4 at (TT-4)-s
            float4 k4 = *(const float4*)&kb[(TT - 4) - s];
            #pragma unroll
            for (int r = 0; r < RPB; ++r) {
                float4 a4 = *(const float4*)&u_s[r * T_LEN + tbase + s];
                acc[r] = fmaf(a4.x, k4.w, acc[r]);
                acc[r] = fmaf(a4.y, k4.z, acc[r]);
                acc[r] = fmaf(a4.z, k4.y, acc[r]);
                acc[r] = fmaf(a4.w, k4.x, acc[r]);
            }
        }
        __syncthreads();
    }

    // ---- cross-q reduction in smem (reuse kb0 region; all compute synced) ----
    float* red = kb0;                          // needs 256*4 floats
    *(float4*)&red[tid * 4] = make_float4(acc[0], acc[1], acc[2], acc[3]);
    __syncthreads();

    const int r_out = tid >> 6;                // 0..3
    const int n_out = tid & 63;
    float v = red[0 * 256 + n_out * 4 + r_out]
            + red[1 * 256 + n_out * 4 + r_out]
            + red[2 * 256 + n_out * 4 + r_out]
            + red[3 * 256 + n_out * 4 + r_out];

    out[(size_t)blockIdx.x * (RPB * N_ORD) + r_out * N_ORD + n_out] = v;
}

extern "C" void kernel_launch(void* const* d_in, const int* in_sizes, int n_in,
                              void* d_out, int out_size)
{
    (void)in_sizes; (void)n_in; (void)out_size;
    const float* U   = (const float*)d_in[0];  // inputs (4,2,64,1024) f32
    const float* K   = (const float*)d_in[1];  // K (64,1024) f32
    float*       out = (float*)d_out;          // (4,2,64,64) f32

    const size_t SMEM = (RPB * T_LEN + 2 * N_ORD * KPITCH) * sizeof(float); // 149504
    // Persistent per-function attribute; set on every call (idempotent). The
    // first (uncaptured) correctness call establishes it even if a captured
    // call were to no-op.
    cudaFuncSetAttribute(hippo_last_kernel,
                         cudaFuncAttributeMaxDynamicSharedMemorySize, (int)SMEM);

    hippo_last_kernel<<<NBLOCKS, THREADS, SMEM>>>(U, K, out);
}

// round 5
// speedup vs baseline: 1.0101x; 1.0101x over previous
#include <cuda_runtime.h>
#include <cstdint>

// out[row, n] = sum_t u[row, t] * K[n, 1023 - t]
//            = sum_j u_rev[row, j] * K[n, j]        (u_rev[j] = u[1023-j])
// Skinny GEMM 512x64x1024, fp32, via packed fma.rn.f32x2 (sm_103a).
// One block = 4 rows x 64 n; t split 8 ways across thread groups q.

#define T_LEN   1024
#define N_ORD   64
#define RPB     4            // rows per block
#define TT      256          // K tile width (t)
#define KPITCH  260          // 260 % 32 == 4 -> conflict-free LDS.128; 1040B = 16B-aligned pitch
#define NTILES  (T_LEN / TT)
#define THREADS 512
#define NBLOCKS (512 / RPB)  // 128

__device__ __forceinline__ void cp_async16(void* dst, const void* src) {
    unsigned s = (unsigned)__cvta_generic_to_shared(dst);
    asm volatile("cp.async.cg.shared.global [%0], [%1], 16;\n" :: "r"(s), "l"(src));
}
__device__ __forceinline__ void cp_commit() {
    asm volatile("cp.async.commit_group;\n");
}
template <int N>
__device__ __forceinline__ void cp_wait() {
    asm volatile("cp.async.wait_group %0;\n" :: "n"(N));
}

// d += a * b, packed 2xf32 (one instruction; ptxas never auto-fuses this)
__device__ __forceinline__ void ffma2(unsigned long long& d,
                                      unsigned long long a,
                                      unsigned long long b) {
    asm("fma.rn.f32x2 %0, %1, %2, %0;" : "+l"(d) : "l"(a), "l"(b));
}

extern __shared__ float smem[];
// layout: u_rev[4*1024] | kbuf0[64*KPITCH] | kbuf1[64*KPITCH]  = 149504 bytes

__global__ void __launch_bounds__(THREADS, 1)
hippo_last_kernel(const float* __restrict__ U,
                  const float* __restrict__ K,
                  float* __restrict__ out)
{
    float* u_s = smem;                           // 4096 floats, time-REVERSED u
    float* kb0 = smem + RPB * T_LEN;
    float* kb1 = kb0 + N_ORD * KPITCH;

    const int tid = threadIdx.x;
    const int q   = tid >> 6;                    // 0..7  (t-eighth within tile)
    const int n   = tid & 63;

    const float* Ublk = U + (size_t)blockIdx.x * RPB * T_LEN;

    // ---- K tile producer: tile i covers K[:, i*TT .. i*TT+TT) (forward) ----
    auto issue_tile = [&](int i, float* kb) {
        const int J0 = TT * i;
        #pragma unroll
        for (int w = 0; w < (N_ORD * TT / 4) / THREADS; ++w) {   // 2
            int idx = tid + THREADS * w;         // 0 .. 4095
            int nn  = idx >> 6;                  // K row
            int c   = (idx & 63) << 2;           // float4 column
            cp_async16(&kb[nn * KPITCH + c], &K[nn * T_LEN + J0 + c]);
        }
        cp_commit();
    };

    // Overlap: kick K tile 0 first, then stream u in (LDG latency hides under TMA-less cp.async)
    issue_tile(0, kb0);

    // ---- load u, storing TIME-REVERSED into smem ----
    {
        const float4* src = (const float4*)Ublk;
        #pragma unroll
        for (int w = 0; w < (RPB * T_LEN / 4) / THREADS; ++w) {  // 2
            int i4  = tid + THREADS * w;         // float4 index
            float4 a = src[i4];
            int row = i4 >> 8;                   // /256 float4s per row
            int t0  = (i4 & 255) << 2;           // element t base
            // u_rev[row][1020 - t0 + {0,1,2,3}] = {a.w, a.z, a.y, a.x}
            float4 r4 = make_float4(a.w, a.z, a.y, a.x);
            *(float4*)&u_s[row * T_LEN + (T_LEN - 4) - t0] = r4;
        }
    }

    issue_tile(1, kb1);
    cp_wait<1>();                                // tile 0 resident
    __syncthreads();                             // + u_rev resident

    unsigned long long accA[RPB] = {0ull, 0ull, 0ull, 0ull};
    unsigned long long accB[RPB] = {0ull, 0ull, 0ull, 0ull};

    #pragma unroll
    for (int i = 0; i < NTILES; ++i) {
        const float* kb = ((i & 1) ? kb1 : kb0) + n * KPITCH;
        const float* ur = u_s + i * TT;

        #pragma unroll
        for (int it = 0; it < 8; ++it) {
            const int s = q * 32 + it * 4;       // local j within tile, 16B-aligned
            ulonglong2 k2 = *(const ulonglong2*)&kb[s];
            #pragma unroll
            for (int r = 0; r < RPB; ++r) {
                ulonglong2 a2 = *(const ulonglong2*)&ur[r * T_LEN + s];
                ffma2(accA[r], a2.x, k2.x);
                ffma2(accB[r], a2.y, k2.y);
            }
        }
        __syncthreads();                         // everyone done with this buffer

        if (i + 2 < NTILES) issue_tile(i + 2, (i & 1) ? kb1 : kb0);
        if (i + 1 < NTILES) {
            if (i + 2 < NTILES) cp_wait<1>(); else cp_wait<0>();
            __syncthreads();
        }
    }

    // ---- fold packed halves, then cross-q reduction in smem (reuse kb0) ----
    float vr[RPB];
    #pragma unroll
    for (int r = 0; r < RPB; ++r) {
        float2 fa = *(float2*)&accA[r];
        float2 fb = *(float2*)&accB[r];
        vr[r] = (fa.x + fa.y) + (fb.x + fb.y);
    }

    __syncthreads();                             // all compute done -> kb0 reusable
    float* red = kb0;                            // 512*4 floats = 8KB
    *(float4*)&red[tid * 4] = make_float4(vr[0], vr[1], vr[2], vr[3]);
    __syncthreads();

    if (tid < 256) {
        const int r_out = tid >> 6;              // 0..3
        const int n_out = tid & 63;
        float v = 0.f;
        #pragma unroll
        for (int qq = 0; qq < 8; ++qq)
            v += red[(qq * 64 + n_out) * 4 + r_out];
        out[(size_t)blockIdx.x * (RPB * N_ORD) + r_out * N_ORD + n_out] = v;
    }
}

extern "C" void kernel_launch(void* const* d_in, const int* in_sizes, int n_in,
                              void* d_out, int out_size)
{
    (void)in_sizes; (void)n_in; (void)out_size;
    const float* U   = (const float*)d_in[0];  // (4,2,64,1024) f32
    const float* K   = (const float*)d_in[1];  // (64,1024) f32
    float*       out = (float*)d_out;          // (4,2,64,64) f32

    const size_t SMEM = (RPB * T_LEN + 2 * N_ORD * KPITCH) * sizeof(float); // 149504
    cudaFuncSetAttribute(hippo_last_kernel,
                         cudaFuncAttributeMaxDynamicSharedMemorySize, (int)SMEM);

    hippo_last_kernel<<<NBLOCKS, THREADS, SMEM>>>(U, K, out);
}

// round 9
// speedup vs baseline: 1.1910x; 1.1791x over previous
#include <cuda_runtime.h>
#include <cstdint>

// out[row, n] = sum_t u[row, t] * K[n, 1023 - t]
//            = sum_j u_rev[row, j] * K[n, j]
// Skinny GEMM 512x64x1024 fp32 via fma.rn.f32x2.
// One-shot kernel: block = 8 rows x 32 n, ENTIRE K slice (32x1024) + u (8x1024)
// resident in smem; single cp.async wait + single barrier, then barrier-free
// mainloop (t split 16 ways across thread groups q).

#define T_LEN   1024
#define N_ORD   64
#define RPB     8            // rows per block
#define NPB     32           // n per block
#define KP      1028         // K smem pitch: 1028 % 32 == 4 -> conflict-free LDS.128
#define THREADS 512
#define NBLOCKS 128          // (512/8) * (64/32)

__device__ __forceinline__ void cp_async16(void* dst, const void* src) {
    unsigned s = (unsigned)__cvta_generic_to_shared(dst);
    asm volatile("cp.async.cg.shared.global [%0], [%1], 16;\n" :: "r"(s), "l"(src));
}
__device__ __forceinline__ void cp_commit() {
    asm volatile("cp.async.commit_group;\n");
}
__device__ __forceinline__ void cp_wait0() {
    asm volatile("cp.async.wait_group 0;\n");
}
// d += a * b, packed 2xf32 (sm_103a; ptxas never auto-fuses this)
__device__ __forceinline__ void ffma2(unsigned long long& d,
                                      unsigned long long a,
                                      unsigned long long b) {
    asm("fma.rn.f32x2 %0, %1, %2, %0;" : "+l"(d) : "l"(a), "l"(b));
}

extern __shared__ float smem[];
// layout: u_rev[8*1024] | K[32*KP]   = (8192 + 32896)*4 = 164352 bytes
// reduction reuses u_rev area after mainloop.

__global__ void __launch_bounds__(THREADS, 1)
hippo_last_kernel(const float* __restrict__ U,
                  const float* __restrict__ K,
                  float* __restrict__ out)
{
    float* u_s = smem;                       // 8192 floats (time-reversed u)
    float* k_s = smem + RPB * T_LEN;         // 32 * KP floats

    const int tid = threadIdx.x;
    const int q   = tid >> 5;                // 0..15 : t-sixteenth
    const int np  = tid & 31;                // n within block

    const int rg = blockIdx.x >> 1;          // row group (8 rows)
    const int h  = blockIdx.x & 1;           // n half

    const float* Ublk = U + (size_t)rg * RPB * T_LEN;
    const float* Kblk = K + (size_t)h * NPB * T_LEN;

    // ---- issue ALL K cp.async first (32 rows x 1024 = 8192 float4) ----
    #pragma unroll
    for (int w = 0; w < (NPB * T_LEN / 4) / THREADS; ++w) {      // 16
        int idx = tid + THREADS * w;         // 0 .. 8191
        int nn  = idx >> 8;                  // K row 0..31
        int c   = (idx & 255) << 2;          // element column
        cp_async16(&k_s[nn * KP + c], &Kblk[nn * T_LEN + c]);
    }
    cp_commit();

    // ---- u: LDG (overlaps K stream), store TIME-REVERSED into smem ----
    {
        const float4* src = (const float4*)Ublk;
        #pragma unroll
        for (int w = 0; w < (RPB * T_LEN / 4) / THREADS; ++w) {  // 4
            int i4  = tid + THREADS * w;     // float4 index
            float4 a = src[i4];
            int row = i4 >> 8;
            int t0  = (i4 & 255) << 2;
            *(float4*)&u_s[row * T_LEN + (T_LEN - 4) - t0] =
                make_float4(a.w, a.z, a.y, a.x);
        }
    }

    cp_wait0();
    __syncthreads();                         // the ONLY pre-mainloop barrier

    // ---- barrier-free mainloop: 64 t per thread, 8 rows, 16 acc chains ----
    unsigned long long accA[RPB], accB[RPB];
    #pragma unroll
    for (int r = 0; r < RPB; ++r) { accA[r] = 0ull; accB[r] = 0ull; }

    const float* kp = k_s + np * KP + q * 64;
    const float* up = u_s + q * 64;

    #pragma unroll
    for (int it = 0; it < 16; ++it) {
        const int s = it * 4;
        ulonglong2 k2 = *(const ulonglong2*)&kp[s];
        #pragma unroll
        for (int r = 0; r < RPB; ++r) {
            ulonglong2 a2 = *(const ulonglong2*)&up[r * T_LEN + s];
            ffma2(accA[r], a2.x, k2.x);
            ffma2(accB[r], a2.y, k2.y);
        }
    }

    // ---- fold packed halves ----
    float vr[RPB];
    #pragma unroll
    for (int r = 0; r < RPB; ++r) {
        float2 fa = *(float2*)&accA[r];
        float2 fb = *(float2*)&accB[r];
        vr[r] = (fa.x + fa.y) + (fb.x + fb.y);
    }

    // ---- cross-q reduction in smem (reuse u_s; 512 threads x 8 floats) ----
    __syncthreads();                         // mainloop reads of u_s done
    *(float4*)&u_s[tid * 8]     = make_float4(vr[0], vr[1], vr[2], vr[3]);
    *(float4*)&u_s[tid * 8 + 4] = make_float4(vr[4], vr[5], vr[6], vr[7]);
    __syncthreads();

    if (tid < RPB * NPB) {                   // 256 outputs
        const int r_out = tid >> 5;          // 0..7
        const int n_out = tid & 31;
        float v = 0.f;
        #pragma unroll
        for (int qq = 0; qq < 16; ++qq)
            v += u_s[(qq * 32 + n_out) * 8 + r_out];
        out[(size_t)(rg * RPB + r_out) * N_ORD + h * NPB + n_out] = v;
    }
}

extern "C" void kernel_launch(void* const* d_in, const int* in_sizes, int n_in,
                              void* d_out, int out_size)
{
    (void)in_sizes; (void)n_in; (void)out_size;
    const float* U   = (const float*)d_in[0];  // (4,2,64,1024) f32
    const float* K   = (const float*)d_in[1];  // (64,1024) f32
    float*       out = (float*)d_out;          // (4,2,64,64) f32

    const size_t SMEM = (RPB * T_LEN + NPB * KP) * sizeof(float); // 164352
    cudaFuncSetAttribute(hippo_last_kernel,
                         cudaFuncAttributeMaxDynamicSharedMemorySize, (int)SMEM);

    hippo_last_kernel<<<NBLOCKS, THREADS, SMEM>>>(U, K, out);
}